// round 8
// baseline (speedup 1.0000x reference)
#include <cuda_runtime.h>
#include <cuda_fp16.h>
#include <math.h>
#include <stdint.h>

#define BB 4
#define SS 2048
#define DD 1024
#define HH 16
#define HDIM 64

// fp16 scratch (device globals: allocation-free per harness rules)
__device__ __half g_h16[BB * SS * DD];
__device__ __half g_wa16[DD * 3 * DD];
__device__ __half g_wp16[DD * DD];
__device__ __half g_qkv16[BB * SS * 3 * DD];
__device__ __half g_ctx16[BB * SS * DD];

// ---------------------------------------------------------------------------
// helpers
// ---------------------------------------------------------------------------
__device__ __forceinline__ uint32_t smem_u32(const void* p) {
    uint32_t a;
    asm("{ .reg .u64 t; cvta.to.shared.u64 t, %1; cvt.u32.u64 %0, t; }"
        : "=r"(a) : "l"(p));
    return a;
}

__device__ __forceinline__ void cpa16(uint32_t dst, const void* src) {
    asm volatile("cp.async.ca.shared.global [%0], [%1], 16;"
                 :: "r"(dst), "l"(src));
}
#define CP_COMMIT() asm volatile("cp.async.commit_group;")
#define CP_WAIT(n)  asm volatile("cp.async.wait_group %0;" :: "n"(n))

__device__ __forceinline__ void ldsm_x4(uint32_t* d, uint32_t addr) {
    asm volatile("ldmatrix.sync.aligned.m8n8.x4.shared.b16 {%0,%1,%2,%3}, [%4];"
                 : "=r"(d[0]), "=r"(d[1]), "=r"(d[2]), "=r"(d[3]) : "r"(addr));
}
__device__ __forceinline__ void ldsm_x4t(uint32_t* d, uint32_t addr) {
    asm volatile("ldmatrix.sync.aligned.m8n8.x4.trans.shared.b16 {%0,%1,%2,%3}, [%4];"
                 : "=r"(d[0]), "=r"(d[1]), "=r"(d[2]), "=r"(d[3]) : "r"(addr));
}

__device__ __forceinline__ void mma_f16(float* c, const uint32_t* a,
                                        uint32_t b0, uint32_t b1) {
    asm volatile(
        "mma.sync.aligned.m16n8k16.row.col.f32.f16.f16.f32 "
        "{%0,%1,%2,%3}, {%4,%5,%6,%7}, {%8,%9}, {%0,%1,%2,%3};"
        : "+f"(c[0]), "+f"(c[1]), "+f"(c[2]), "+f"(c[3])
        : "r"(a[0]), "r"(a[1]), "r"(a[2]), "r"(a[3]), "r"(b0), "r"(b1));
}

__device__ __forceinline__ uint32_t h2bits(float x, float y) {
    __half2 h = __floats2half2_rn(x, y);
    return *reinterpret_cast<uint32_t*>(&h);
}

// ---------------------------------------------------------------------------
// fp32 -> fp16 conversion
// ---------------------------------------------------------------------------
__global__ void f32_to_f16_kernel(const float4* __restrict__ src,
                                  uint2* __restrict__ dst, int n4)
{
    int i = blockIdx.x * blockDim.x + threadIdx.x;
    if (i < n4) {
        float4 v = src[i];
        uint2 u;
        u.x = h2bits(v.x, v.y);
        u.y = h2bits(v.z, v.w);
        dst[i] = u;
    }
}

// ---------------------------------------------------------------------------
// fp16 GEMM v3: CTA 128x256, BK=64, 8 warps (2x4), warp tile 64x64.
// cp.async double-buffered; A stride 72 halves, B stride 264 halves.
// 8 ldsm.x4 per 32 MMAs (0.25/MMA) -> smem no longer the binding pipe.
// ---------------------------------------------------------------------------
#define GLDA 72
#define GLDB 264
#define ABUF_B (128 * GLDA * 2)                 // 18432
#define BBUF_B (64 * GLDB * 2)                  // 33792
#define GSMEM_TOTAL (2 * ABUF_B + 2 * BBUF_B)   // 104448

template<int OUT16>
__global__ __launch_bounds__(256, 1)
void gemm_f16_v3(const __half* __restrict__ A, const __half* __restrict__ W,
                 const float* __restrict__ bias, void* __restrict__ Cout,
                 int M, int N, int K)
{
    extern __shared__ char gsm[];
    __half* As[2] = { (__half*)gsm, (__half*)(gsm + ABUF_B) };
    __half* Bs[2] = { (__half*)(gsm + 2 * ABUF_B),
                      (__half*)(gsm + 2 * ABUF_B + BBUF_B) };

    const int tid  = threadIdx.x;
    const int warp = tid >> 5;
    const int lane = tid & 31;
    const int gid  = lane >> 2;
    const int tig  = lane & 3;
    const int wm = warp >> 2;          // 0..1 -> 64-row block
    const int wn = warp & 3;           // 0..3 -> 64-col block

    const int row0 = blockIdx.y * 128;
    const int col0 = blockIdx.x * 256;

    float acc[4][8][4];
    #pragma unroll
    for (int a = 0; a < 4; a++)
        #pragma unroll
        for (int j = 0; j < 8; j++)
            #pragma unroll
            for (int v = 0; v < 4; v++) acc[a][j][v] = 0.f;

    #define GSTAGE(BUF, KT)                                                   \
        do {                                                                  \
            _Pragma("unroll")                                                 \
            for (int j = 0; j < 4; j++) {                                     \
                int idx = j * 256 + tid;                                      \
                int r = idx >> 3, c = idx & 7;                                \
                cpa16(smem_u32(&As[BUF][r * GLDA + c * 8]),                   \
                      A + (size_t)(row0 + r) * K + (KT) * 64 + c * 8);        \
            }                                                                 \
            _Pragma("unroll")                                                 \
            for (int j = 0; j < 8; j++) {                                     \
                int idx = j * 256 + tid;                                      \
                int kr = idx >> 5, c = idx & 31;                              \
                cpa16(smem_u32(&Bs[BUF][kr * GLDB + c * 8]),                  \
                      W + (size_t)((KT) * 64 + kr) * N + col0 + c * 8);       \
            }                                                                 \
        } while (0)

    const int i = lane;
    const int a_lrow = wm * 64 + (i & 7) + ((i >> 3) & 1) * 8;
    const int a_lk   = ((i >> 4) & 1) * 8;
    const int b_lk   = (i & 7) + ((i >> 3) & 1) * 8;
    const int b_lc   = wn * 64 + ((i >> 4) & 1) * 8;

    GSTAGE(0, 0);
    CP_COMMIT();

    const int NT = K / 64;
    int buf = 0;
    for (int t = 0; t < NT; t++) {
        if (t + 1 < NT) {
            GSTAGE(buf ^ 1, t + 1);
            CP_COMMIT();
            CP_WAIT(1);
        } else {
            CP_WAIT(0);
        }
        __syncthreads();

        const uint32_t abase = smem_u32(&As[buf][a_lrow * GLDA + a_lk]);
        const uint32_t bbase = smem_u32(&Bs[buf][b_lk * GLDB + b_lc]);
        #pragma unroll
        for (int ks = 0; ks < 4; ks++) {
            uint32_t af[4][4];
            #pragma unroll
            for (int mi = 0; mi < 4; mi++)
                ldsm_x4(af[mi], abase + mi * 16 * GLDA * 2 + ks * 32);
            uint32_t bf[4][4];
            #pragma unroll
            for (int nb = 0; nb < 4; nb++)
                ldsm_x4t(bf[nb], bbase + (ks * 16 * GLDB + nb * 16) * 2);
            #pragma unroll
            for (int nb = 0; nb < 4; nb++)
                #pragma unroll
                for (int hn = 0; hn < 2; hn++) {
                    int ni = nb * 2 + hn;
                    #pragma unroll
                    for (int mi = 0; mi < 4; mi++)
                        mma_f16(acc[mi][ni], af[mi],
                                bf[nb][hn * 2], bf[nb][hn * 2 + 1]);
                }
        }
        __syncthreads();
        buf ^= 1;
    }

    #pragma unroll
    for (int mi = 0; mi < 4; mi++) {
        int r = row0 + wm * 64 + mi * 16 + gid;
        #pragma unroll
        for (int ni = 0; ni < 8; ni++) {
            int c = col0 + wn * 64 + ni * 8 + 2 * tig;
            float bx = __ldg(&bias[c]);
            float by = __ldg(&bias[c + 1]);
            if (OUT16) {
                __half* C16 = (__half*)Cout;
                __half2 h0 = __floats2half2_rn(acc[mi][ni][0] + bx,
                                               acc[mi][ni][1] + by);
                __half2 h1 = __floats2half2_rn(acc[mi][ni][2] + bx,
                                               acc[mi][ni][3] + by);
                *reinterpret_cast<__half2*>(&C16[(size_t)r * N + c]) = h0;
                *reinterpret_cast<__half2*>(&C16[(size_t)(r + 8) * N + c]) = h1;
            } else {
                float* C32 = (float*)Cout;
                float2 o0 = make_float2(acc[mi][ni][0] + bx, acc[mi][ni][1] + by);
                float2 o1 = make_float2(acc[mi][ni][2] + bx, acc[mi][ni][3] + by);
                *reinterpret_cast<float2*>(&C32[(size_t)r * N + c]) = o0;
                *reinterpret_cast<float2*>(&C32[(size_t)(r + 8) * N + c]) = o1;
            }
        }
    }
}

// ---------------------------------------------------------------------------
// fp16 flash attention v2 (unchanged from R7): 128 queries/CTA, 8 warps,
// 64-key tiles double-buffered via cp.async.
// ---------------------------------------------------------------------------
#define AST 72
#define Q_BYTES (128 * AST * 2)
#define KV_BYTES (64 * AST * 2)
#define ASMEM_TOTAL (Q_BYTES + 4 * KV_BYTES)

__global__ __launch_bounds__(256)
void attn_f16_v2(const __half* __restrict__ qkv, __half* __restrict__ ctx)
{
    extern __shared__ char smraw[];
    __half* Qs = (__half*)smraw;
    __half* Ks[2] = { (__half*)(smraw + Q_BYTES),
                      (__half*)(smraw + Q_BYTES + KV_BYTES) };
    __half* Vs[2] = { (__half*)(smraw + Q_BYTES + 2 * KV_BYTES),
                      (__half*)(smraw + Q_BYTES + 3 * KV_BYTES) };

    const int bh = blockIdx.x;
    const int b  = bh / HH;
    const int h  = bh % HH;
    const int qt = gridDim.y - 1 - blockIdx.y;
    const int q0 = qt * 128;

    const int tid  = threadIdx.x;
    const int warp = tid >> 5;
    const int lane = tid & 31;
    const int gid  = lane >> 2;
    const int tig  = lane & 3;
    const int wr0  = warp * 16;

    #define ASTAGE(BUF, K0)                                                   \
        do {                                                                  \
            _Pragma("unroll")                                                 \
            for (int j = 0; j < 2; j++) {                                     \
                int idx = j * 256 + tid;                                      \
                int r = idx >> 3, c = idx & 7;                                \
                const __half* kp = qkv                                        \
                    + ((size_t)(b * SS + (K0) + r)) * (3 * DD)                \
                    + DD + h * HDIM + c * 8;                                  \
                cpa16(smem_u32(&Ks[BUF][r * AST + c * 8]), kp);               \
                cpa16(smem_u32(&Vs[BUF][r * AST + c * 8]), kp + DD);          \
            }                                                                 \
        } while (0)

    ASTAGE(0, 0);
    CP_COMMIT();
    #pragma unroll
    for (int j = 0; j < 4; j++) {
        int idx = j * 256 + tid;
        int r = idx >> 3, c = idx & 7;
        uint4 v = *reinterpret_cast<const uint4*>(
            qkv + ((size_t)(b * SS + q0 + r)) * (3 * DD) + h * HDIM + c * 8);
        *reinterpret_cast<uint4*>(&Qs[r * AST + c * 8]) = v;
    }
    __syncthreads();

    const int i = lane;
    uint32_t qa[4][4];
    {
        uint32_t qbase = smem_u32(
            &Qs[(wr0 + (i & 7) + ((i >> 3) & 1) * 8) * AST + ((i >> 4) & 1) * 8]);
        #pragma unroll
        for (int ks = 0; ks < 4; ks++) ldsm_x4(qa[ks], qbase + ks * 32);
    }

    const int k_lrow = (i & 7) + ((i >> 4) & 1) * 8;
    const int k_ld   = ((i >> 3) & 1) * 8;
    const int v_lrow = (i & 7) + ((i >> 3) & 1) * 8;
    const int v_ld   = ((i >> 4) & 1) * 8;

    float oacc[8][4];
    #pragma unroll
    for (int a = 0; a < 8; a++)
        #pragma unroll
        for (int v = 0; v < 4; v++) oacc[a][v] = 0.f;
    float m0 = -1e30f, m1 = -1e30f, l0 = 0.f, l1 = 0.f;

    const int nt = q0 / 64 + 2;
    const int warp_maxrow = q0 + wr0 + 15;
    int buf = 0;
    for (int t = 0; t < nt; t++) {
        const int k0 = t * 64;
        if (t + 1 < nt) {
            ASTAGE(buf ^ 1, (t + 1) * 64);
            CP_COMMIT();
            CP_WAIT(1);
        } else {
            CP_WAIT(0);
        }
        __syncthreads();

        if (k0 <= warp_maxrow) {
            const uint32_t kbase = smem_u32(&Ks[buf][k_lrow * AST + k_ld]);
            const uint32_t vbase = smem_u32(&Vs[buf][v_lrow * AST + v_ld]);

            float sacc[8][4];
            #pragma unroll
            for (int ni = 0; ni < 8; ni++)
                sacc[ni][0] = sacc[ni][1] = sacc[ni][2] = sacc[ni][3] = 0.f;
            #pragma unroll
            for (int ks = 0; ks < 4; ks++) {
                #pragma unroll
                for (int kt = 0; kt < 4; kt++) {
                    uint32_t kf[4];
                    ldsm_x4(kf, kbase + (kt * 16 * AST + ks * 16) * 2);
                    mma_f16(sacc[kt * 2 + 0], qa[ks], kf[0], kf[1]);
                    mma_f16(sacc[kt * 2 + 1], qa[ks], kf[2], kf[3]);
                }
            }

            const int rg0 = q0 + wr0 + gid;
            const bool need_mask = (k0 + 63 > q0 + wr0);
            #pragma unroll
            for (int ni = 0; ni < 8; ni++) {
                #pragma unroll
                for (int v = 0; v < 4; v++) sacc[ni][v] *= 0.125f;
                if (need_mask) {
                    int cg = k0 + ni * 8 + 2 * tig;
                    if (cg     > rg0)     sacc[ni][0] = -1e30f;
                    if (cg + 1 > rg0)     sacc[ni][1] = -1e30f;
                    if (cg     > rg0 + 8) sacc[ni][2] = -1e30f;
                    if (cg + 1 > rg0 + 8) sacc[ni][3] = -1e30f;
                }
            }

            float tmax0 = -1e30f, tmax1 = -1e30f;
            #pragma unroll
            for (int ni = 0; ni < 8; ni++) {
                tmax0 = fmaxf(tmax0, fmaxf(sacc[ni][0], sacc[ni][1]));
                tmax1 = fmaxf(tmax1, fmaxf(sacc[ni][2], sacc[ni][3]));
            }
            tmax0 = fmaxf(tmax0, __shfl_xor_sync(0xffffffffu, tmax0, 1));
            tmax0 = fmaxf(tmax0, __shfl_xor_sync(0xffffffffu, tmax0, 2));
            tmax1 = fmaxf(tmax1, __shfl_xor_sync(0xffffffffu, tmax1, 1));
            tmax1 = fmaxf(tmax1, __shfl_xor_sync(0xffffffffu, tmax1, 2));

            float mn0 = fmaxf(m0, tmax0);
            float mn1 = fmaxf(m1, tmax1);
            float c0 = __expf(m0 - mn0);
            float c1 = __expf(m1 - mn1);
            m0 = mn0; m1 = mn1;

            float s0 = 0.f, s1 = 0.f;
            #pragma unroll
            for (int ni = 0; ni < 8; ni++) {
                sacc[ni][0] = __expf(sacc[ni][0] - mn0);
                sacc[ni][1] = __expf(sacc[ni][1] - mn0);
                sacc[ni][2] = __expf(sacc[ni][2] - mn1);
                sacc[ni][3] = __expf(sacc[ni][3] - mn1);
                s0 += sacc[ni][0] + sacc[ni][1];
                s1 += sacc[ni][2] + sacc[ni][3];
                oacc[ni][0] *= c0; oacc[ni][1] *= c0;
                oacc[ni][2] *= c1; oacc[ni][3] *= c1;
            }
            s0 += __shfl_xor_sync(0xffffffffu, s0, 1);
            s0 += __shfl_xor_sync(0xffffffffu, s0, 2);
            s1 += __shfl_xor_sync(0xffffffffu, s1, 1);
            s1 += __shfl_xor_sync(0xffffffffu, s1, 2);
            l0 = l0 * c0 + s0;
            l1 = l1 * c1 + s1;

            #pragma unroll
            for (int s = 0; s < 4; s++) {
                uint32_t pa[4];
                pa[0] = h2bits(sacc[2 * s][0],     sacc[2 * s][1]);
                pa[1] = h2bits(sacc[2 * s][2],     sacc[2 * s][3]);
                pa[2] = h2bits(sacc[2 * s + 1][0], sacc[2 * s + 1][1]);
                pa[3] = h2bits(sacc[2 * s + 1][2], sacc[2 * s + 1][3]);
                #pragma unroll
                for (int db = 0; db < 4; db++) {
                    uint32_t vf[4];
                    ldsm_x4t(vf, vbase + (s * 16 * AST + db * 16) * 2);
                    mma_f16(oacc[db * 2 + 0], pa, vf[0], vf[1]);
                    mma_f16(oacc[db * 2 + 1], pa, vf[2], vf[3]);
                }
            }
        }
        __syncthreads();
        buf ^= 1;
    }

    float inv0 = 1.f / l0;
    float inv1 = 1.f / l1;
    int row0 = q0 + wr0 + gid;
    int row1 = row0 + 8;
    #pragma unroll
    for (int ni = 0; ni < 8; ni++) {
        int d = h * HDIM + ni * 8 + 2 * tig;
        __half2 h0 = __floats2half2_rn(oacc[ni][0] * inv0, oacc[ni][1] * inv0);
        __half2 h1 = __floats2half2_rn(oacc[ni][2] * inv1, oacc[ni][3] * inv1);
        *reinterpret_cast<__half2*>(&ctx[((size_t)(b * SS + row0)) * DD + d]) = h0;
        *reinterpret_cast<__half2*>(&ctx[((size_t)(b * SS + row1)) * DD + d]) = h1;
    }
}

// ---------------------------------------------------------------------------
// Launch
// ---------------------------------------------------------------------------
extern "C" void kernel_launch(void* const* d_in, const int* in_sizes, int n_in,
                              void* d_out, int out_size)
{
    const float* hidden = (const float*)d_in[0];
    const float* w_attn = (const float*)d_in[1];
    const float* b_attn = (const float*)d_in[2];
    const float* w_proj = (const float*)d_in[3];
    const float* b_proj = (const float*)d_in[4];
    float* out = (float*)d_out;

    __half *h16, *wa16, *wp16, *qkv16, *ctx16;
    cudaGetSymbolAddress((void**)&h16,   g_h16);
    cudaGetSymbolAddress((void**)&wa16,  g_wa16);
    cudaGetSymbolAddress((void**)&wp16,  g_wp16);
    cudaGetSymbolAddress((void**)&qkv16, g_qkv16);
    cudaGetSymbolAddress((void**)&ctx16, g_ctx16);

    static bool attr_done = false;
    if (!attr_done) {
        cudaFuncSetAttribute(gemm_f16_v3<1>,
                             cudaFuncAttributeMaxDynamicSharedMemorySize,
                             GSMEM_TOTAL);
        cudaFuncSetAttribute(gemm_f16_v3<0>,
                             cudaFuncAttributeMaxDynamicSharedMemorySize,
                             GSMEM_TOTAL);
        cudaFuncSetAttribute(attn_f16_v2,
                             cudaFuncAttributeMaxDynamicSharedMemorySize,
                             ASMEM_TOTAL);
        attr_done = true;
    }

    const int M = BB * SS;   // 8192

    // 0) fp32 -> fp16 conversions
    {
        int n4 = BB * SS * DD / 4;
        f32_to_f16_kernel<<<(n4 + 255) / 256, 256>>>(
            (const float4*)hidden, (uint2*)h16, n4);
        n4 = DD * 3 * DD / 4;
        f32_to_f16_kernel<<<(n4 + 255) / 256, 256>>>(
            (const float4*)w_attn, (uint2*)wa16, n4);
        n4 = DD * DD / 4;
        f32_to_f16_kernel<<<(n4 + 255) / 256, 256>>>(
            (const float4*)w_proj, (uint2*)wp16, n4);
    }

    // 1) qkv16 = h16 @ wa16 + b_attn
    {
        dim3 grid(3 * DD / 256, M / 128);
        gemm_f16_v3<1><<<grid, 256, GSMEM_TOTAL>>>(h16, wa16, b_attn, qkv16,
                                                   M, 3 * DD, DD);
    }

    // 2) ctx16 = causal_attention(qkv16)
    {
        dim3 grid(BB * HH, SS / 128);
        attn_f16_v2<<<grid, 256, ASMEM_TOTAL>>>(qkv16, ctx16);
    }

    // 3) out = ctx16 @ wp16 + b_proj (fp32 out)
    {
        dim3 grid(DD / 256, M / 128);
        gemm_f16_v3<0><<<grid, 256, GSMEM_TOTAL>>>(ctx16, wp16, b_proj, out,
                                                   M, DD, DD);
    }
}